// round 5
// baseline (speedup 1.0000x reference)
#include <cuda_runtime.h>

#define NSTEP  25
#define NIN    9
#define NHID   100

__global__ __launch_bounds__(64) void snn_kernel(
    const float* __restrict__ x,
    const float* __restrict__ W1,
    const float* __restrict__ b1,
    const float* __restrict__ W2,
    const float* __restrict__ b2,
    float* __restrict__ out,
    int batch)
{
    // W1 padded to 12 floats/row: [w0..w8, b1, 0, 0] -> 3x LDS.128 per neuron
    __shared__ float4 sW1[NHID * 3];
    __shared__ float2 sW2[NHID];   // (W2[0][h], W2[1][h])
    __shared__ float  sb2[2];

    {
        float* sW1f = (float*)sW1;
        for (int h = threadIdx.x; h < NHID; h += blockDim.x) {
#pragma unroll
            for (int i = 0; i < NIN; i++) sW1f[h * 12 + i] = W1[h * NIN + i];
            sW1f[h * 12 + 9]  = b1[h];
            sW1f[h * 12 + 10] = 0.0f;
            sW1f[h * 12 + 11] = 0.0f;
            sW2[h] = make_float2(W2[h], W2[NHID + h]);
        }
        if (threadIdx.x < 2) sb2[threadIdx.x] = b2[threadIdx.x];
    }
    __syncthreads();

    int b = blockIdx.x * blockDim.x + threadIdx.x;
    if (b >= batch) return;

    float xv[NIN];
#pragma unroll
    for (int i = 0; i < NIN; i++) xv[i] = __ldg(&x[(size_t)b * NIN + i]);

    // Packed layer-2 input accumulators over timestep PAIRS:
    //   A0[k] = (acc_out0[2k], acc_out0[2k+1]),  A1[k] likewise for out1.
    unsigned long long A0[12], A1[12];
    float acc0t = 0.0f, acc1t = 0.0f;          // tail step t=24
#pragma unroll
    for (int k = 0; k < 12; k++) { A0[k] = 0ULL; A1[k] = 0ULL; }

    // 25 groups of 4 neurons; 4 independent recurrence chains per group.
    for (int g = 0; g < NHID / 4; g++) {
        const int h = g * 4;
        float c[4];
        float2 w[4];
        unsigned long long w0d[4], w1d[4];     // (w,w) duplicated packs
#pragma unroll
        for (int j = 0; j < 4; j++) {
            float4 a0 = sW1[(h + j) * 3 + 0];
            float4 a1 = sW1[(h + j) * 3 + 1];
            float4 a2 = sW1[(h + j) * 3 + 2];
            float cc = a2.y;                   // bias in padded slot 9
            cc = fmaf(xv[0], a0.x, cc); cc = fmaf(xv[1], a0.y, cc);
            cc = fmaf(xv[2], a0.z, cc); cc = fmaf(xv[3], a0.w, cc);
            cc = fmaf(xv[4], a1.x, cc); cc = fmaf(xv[5], a1.y, cc);
            cc = fmaf(xv[6], a1.z, cc); cc = fmaf(xv[7], a1.w, cc);
            cc = fmaf(xv[8], a2.x, cc);
            c[j] = cc;
            w[j] = sW2[h + j];
            asm("mov.b64 %0, {%1, %1};" : "=l"(w0d[j]) : "f"(w[j].x));
            asm("mov.b64 %0, {%1, %1};" : "=l"(w1d[j]) : "f"(w[j].y));
        }

        float m[4] = {0.f, 0.f, 0.f, 0.f};     // membranes
        float r[4] = {0.f, 0.f, 0.f, 0.f};     // spikes (float 0/1)

        // 12 timestep pairs. Per neuron per 2 steps (8 instr):
        //   2x FFMA-imm (beta*m + c), 2x FADD (-r), 2x FSET (spike),
        //   2x FFMA2 (packed acc over the step pair, both outputs).
#pragma unroll
        for (int k = 0; k < 12; k++) {
#pragma unroll
            for (int j = 0; j < 4; j++) {
                float ra, rb;
                m[j] = fmaf(0.95f, m[j], c[j]) - r[j];
                asm("set.gt.f32.f32 %0, %1, 0f3F800000;" : "=f"(ra) : "f"(m[j]));
                m[j] = fmaf(0.95f, m[j], c[j]) - ra;
                asm("set.gt.f32.f32 %0, %1, 0f3F800000;" : "=f"(rb) : "f"(m[j]));
                r[j] = rb;
                unsigned long long sp;
                asm("mov.b64 %0, {%1, %2};" : "=l"(sp) : "f"(ra), "f"(rb));
                asm("fma.rn.f32x2 %0, %1, %2, %0;" : "+l"(A0[k]) : "l"(sp), "l"(w0d[j]));
                asm("fma.rn.f32x2 %0, %1, %2, %0;" : "+l"(A1[k]) : "l"(sp), "l"(w1d[j]));
            }
        }
        // tail step t=24 (scalar)
#pragma unroll
        for (int j = 0; j < 4; j++) {
            m[j] = fmaf(0.95f, m[j], c[j]) - r[j];
            float rt;
            asm("set.gt.f32.f32 %0, %1, 0f3F800000;" : "=f"(rt) : "f"(m[j]));
            acc0t = fmaf(rt, w[j].x, acc0t);
            acc1t = fmaf(rt, w[j].y, acc1t);
        }
    }

    // Layer-2 LIF recurrence + record mem2 each step
    const float bb0 = sb2[0], bb1 = sb2[1];
    float m20 = 0.0f, m21 = 0.0f;
    float2* outv = (float2*)out;
#pragma unroll
    for (int t = 0; t < NSTEP; t++) {
        float a0f, a1f;
        if (t < 24) {
            float lo, hi;
            asm("mov.b64 {%0, %1}, %2;" : "=f"(lo), "=f"(hi) : "l"(A0[t >> 1]));
            a0f = (t & 1) ? hi : lo;
            asm("mov.b64 {%0, %1}, %2;" : "=f"(lo), "=f"(hi) : "l"(A1[t >> 1]));
            a1f = (t & 1) ? hi : lo;
        } else {
            a0f = acc0t;
            a1f = acc1t;
        }
        float rr0, rr1;                        // reset from PREVIOUS mem2
        asm("set.gt.f32.f32 %0, %1, 0f3F800000;" : "=f"(rr0) : "f"(m20));
        asm("set.gt.f32.f32 %0, %1, 0f3F800000;" : "=f"(rr1) : "f"(m21));
        m20 = fmaf(0.95f, m20, a0f + bb0) - rr0;
        m21 = fmaf(0.95f, m21, a1f + bb1) - rr1;
        outv[(size_t)t * batch + b] = make_float2(m20, m21);
    }
}

extern "C" void kernel_launch(void* const* d_in, const int* in_sizes, int n_in,
                              void* d_out, int out_size)
{
    const float* x  = (const float*)d_in[0];
    const float* W1 = (const float*)d_in[1];
    const float* b1 = (const float*)d_in[2];
    const float* W2 = (const float*)d_in[3];
    const float* b2 = (const float*)d_in[4];
    float* out = (float*)d_out;

    int batch = in_sizes[0] / NIN;
    const int threads = 64;
    int blocks = (batch + threads - 1) / threads;
    snn_kernel<<<blocks, threads>>>(x, W1, b1, W2, b2, out, batch);
}